// round 14
// baseline (speedup 1.0000x reference)
#include <cuda_runtime.h>
#include <cuda_bf16.h>
#include <cstdint>

// Problem constants
#define VOCAB 50000
#define MPAD  50048              // 391 * 128
#define EMB   300
#define FILT  400
#define ATT   200
#define KW    3
#define BATCH 4096
#define SEQ   30
#define M2    (BATCH * SEQ)      // 122880
#define GN    1280               // 3*400 padded to 1280
#define NPAD  256                // ATT padded 200 -> 256

// GEMM1: virtual K = 960 (3 terms x 320); A stored as [hi|lo] = 640 cols,
//        third (hi) term redirected to cols 0..319 (uniform wrap at c>=10).
#define KV1   960
#define KSA1  640
#define KB1   960
#define NC1   15                 // 960/64
#define NREAL1 1200              // real N columns of gemm_P output
// GEMM2: virtual K = 1216 (hi|lo|hi|pad16); A stored as [hi|lo|zero32] = 832.
#define KV2   1216
#define KSA2  832
#define KB2   1216
#define NC2   19                 // 1216/64
#define NREAL2 200               // real attention columns

// ---------------------------------------------------------------------------
// Scratch (static device globals; zero-initialized at module load)
// ---------------------------------------------------------------------------
__device__ __nv_bfloat16 g_Abf[(size_t)MPAD * KSA1]; // emb split [hi|lo]
__device__ __nv_bfloat16 g_Bbf[(size_t)GN * KB1];    // G split  [hi;hi;lo], [N][K]
__device__ float         g_P[(size_t)VOCAB * GN];    // vocab projection fp32
__device__ __nv_bfloat16 g_Cbf[(size_t)M2 * KSA2];   // relu(conv) split [hi|lo|0]
__device__ __nv_bfloat16 g_VPbf[(size_t)NPAD * KB2]; // v split [hi|hi|lo|0], [N][K]
__device__ float         g_vbp[NPAD];
__device__ float         g_qp[NPAD];
__device__ float         g_scorep[2 * M2];
__device__ float         g_alpha[M2];

// ---------------------------------------------------------------------------
// Kernel 0: build bf16-split operands + padded attention weights (32-bit idx).
// ---------------------------------------------------------------------------
__global__ void prep_kernel(const float* __restrict__ emb,
                            const float* __restrict__ conv_w,
                            const float* __restrict__ v,
                            const float* __restrict__ vb,
                            const float* __restrict__ q)
{
    uint32_t i      = blockIdx.x * blockDim.x + threadIdx.x;
    uint32_t stride = gridDim.x * blockDim.x;

    // A' = emb split: [hi (0..319) | lo (320..639)]; pad k 300..319 zero
    for (uint32_t idx = i; idx < (uint32_t)VOCAB * KSA1; idx += stride) {
        uint32_t m  = idx / KSA1;
        uint32_t kp = idx - m * KSA1;
        uint32_t t  = kp / 320, k = kp - t * 320;
        float out = 0.f;
        if (k < EMB) {
            float x  = emb[m * EMB + k];
            float hi = __bfloat162float(__float2bfloat16(x));
            out = t ? (x - hi) : hi;
        }
        g_Abf[idx] = __float2bfloat16(out);
    }

    // B' = G split, N-major: n = kk*400+f, G[k][n] = conv_w[f][k][kk]; {hi,hi,lo}
    for (uint32_t idx = i; idx < (uint32_t)GN * KB1; idx += stride) {
        uint32_t n  = idx / KB1;
        uint32_t kp = idx - n * KB1;
        uint32_t t  = kp / 320, k = kp - t * 320;
        float out = 0.f;
        if (k < EMB && n < KW * FILT) {
            uint32_t kk = n / FILT, f = n - kk * FILT;
            float x  = conv_w[f * (EMB * KW) + k * KW + kk];
            float hi = __bfloat162float(__float2bfloat16(x));
            out = (t == 2) ? (x - hi) : hi;
        }
        g_Bbf[idx] = __float2bfloat16(out);
    }

    // VP' = v split, N-major: VP'[a][t*400+f] from v[f][a]; {hi,hi,lo}
    for (uint32_t idx = i; idx < (uint32_t)NPAD * KB2; idx += stride) {
        uint32_t a  = idx / KB2;
        uint32_t kp = idx - a * KB2;
        float out = 0.f;
        if (kp < 1200 && a < ATT) {
            uint32_t t = kp / 400, f = kp - t * 400;
            float x  = v[f * ATT + a];
            float hi = __bfloat162float(__float2bfloat16(x));
            out = (t == 2) ? (x - hi) : hi;
        }
        g_VPbf[idx] = __float2bfloat16(out);
    }

    if (i < NPAD) {
        g_vbp[i] = (i < ATT) ? vb[i] : 0.f;
        g_qp[i]  = (i < ATT) ? q[i]  : 0.f;
    }
}

// ---------------------------------------------------------------------------
// HMMA helpers (sm_80-era instructions: compile on family target)
// ---------------------------------------------------------------------------
__device__ __forceinline__ uint32_t smem_u32(const void* p) {
    uint32_t r;
    asm("{ .reg .u64 t; cvta.to.shared.u64 t, %1; cvt.u32.u64 %0, t; }"
        : "=r"(r) : "l"(p));
    return r;
}
#define SWZ(x) ((x) ^ (((x) >> 3) & 0x70))

__device__ __forceinline__ void ldm4(uint32_t* r, uint32_t addr) {
    asm volatile("ldmatrix.sync.aligned.m8n8.x4.shared.b16 {%0,%1,%2,%3}, [%4];"
                 : "=r"(r[0]), "=r"(r[1]), "=r"(r[2]), "=r"(r[3]) : "r"(addr));
}
__device__ __forceinline__ void mma16816(float* c, const uint32_t* a,
                                         uint32_t b0, uint32_t b1) {
    asm volatile(
        "mma.sync.aligned.m16n8k16.row.col.f32.bf16.bf16.f32 "
        "{%0,%1,%2,%3}, {%4,%5,%6,%7}, {%8,%9}, {%0,%1,%2,%3};"
        : "+f"(c[0]), "+f"(c[1]), "+f"(c[2]), "+f"(c[3])
        : "r"(a[0]), "r"(a[1]), "r"(a[2]), "r"(a[3]), "r"(b0), "r"(b1));
}
__device__ __forceinline__ void cpasync16(uint32_t s, const void* g) {
    asm volatile(
        "{ .reg .u64 ga; cvta.to.global.u64 ga, %1; "
        "cp.async.cg.shared.global [%0], [ga], 16; }"
        :: "r"(s), "l"(g) : "memory");
}
#define CP_COMMIT() asm volatile("cp.async.commit_group;" ::: "memory")
#define CP_WAIT1()  asm volatile("cp.async.wait_group 1;" ::: "memory")
#define CP_WAIT0()  asm volatile("cp.async.wait_group 0;" ::: "memory")

#define STG_BYTES 32768          // 16KB A + 16KB B per stage
#define DYN_SMEM  (3 * STG_BYTES)

// Loop-invariant ldmatrix address components; warp layout 2(m) x 4(n).
struct LdmAddr {
    uint32_t aoff[4], axm[4];
    uint32_t boff[2], bxm[2];
    uint32_t colk[4];
};
__device__ __forceinline__ LdmAddr make_ldm(int wm, int wn, int lane) {
    LdmAddr L;
#pragma unroll
    for (int mi = 0; mi < 4; mi++) {
        int r = wm + mi * 16 + (lane & 15);
        L.aoff[mi] = (uint32_t)r * 128;
        L.axm[mi]  = ((uint32_t)r << 4) & 0x70;
    }
#pragma unroll
    for (int bj = 0; bj < 2; bj++) {
        int r = wn + bj * 16 + (lane & 15);
        L.boff[bj] = 16384u + (uint32_t)r * 128;
        L.bxm[bj]  = ((uint32_t)r << 4) & 0x70;
    }
#pragma unroll
    for (int ks = 0; ks < 4; ks++)
        L.colk[ks] = (uint32_t)ks * 32 + ((lane >> 4) << 4);
    return L;
}

// One chunk of MMA work; nlim = # of real nb tiles (0..4, uniform per warp),
// ko = per-warp ks phase offset (staggers SMSP-sharing warps).
__device__ __forceinline__ void mma_chunk(uint32_t sbuf, const LdmAddr& L,
                                          float acc[4][4][4], int nlim, int ko) {
    if (nlim == 0) return;
#pragma unroll
    for (int i = 0; i < 4; i++) {
        int ks = (i + ko) & 3;
        uint32_t af[4][4], bf2[2][4];
#pragma unroll
        for (int mi = 0; mi < 4; mi++)
            ldm4(af[mi], sbuf + L.aoff[mi] + (L.colk[ks] ^ L.axm[mi]));
#pragma unroll
        for (int bj = 0; bj < 2; bj++)
            if (nlim > 2 * bj)
                ldm4(bf2[bj], sbuf + L.boff[bj] + (L.colk[ks] ^ L.bxm[bj]));
#pragma unroll
        for (int mi = 0; mi < 4; mi++)
#pragma unroll
            for (int nb = 0; nb < 4; nb++)
                if (nb < nlim)
                    mma16816(acc[mi][nb], af[mi],
                             bf2[nb >> 1][nb & 1], bf2[nb >> 1][(nb & 1) + 2]);
    }
}

__device__ __forceinline__ int nlim_of(int nreal, int bN, int wn) {
    int d = nreal - bN - wn;
    int n = (d + 7) >> 3;
    return (n < 0) ? 0 : ((n > 4) ? 4 : n);
}

// ---------------------------------------------------------------------------
// GEMM 1 (HMMA): g_P[50048 x 1280] = A'[.,960]virt @ B'^T, fp32 accum.
// ---------------------------------------------------------------------------
__global__ __launch_bounds__(256, 2) void gemm_P_mma()
{
    extern __shared__ __align__(128) uint8_t dyn[];
    int tid = threadIdx.x, w = tid >> 5, lane = tid & 31;
    int bM = blockIdx.y * 128, bN = blockIdx.x * 128;
    int wm = (w & 1) * 64, wn = (w >> 1) * 32;
    uint32_t sbase = smem_u32(dyn);
    LdmAddr L = make_ldm(wm, wn, lane);
    int nlim = nlim_of(NREAL1, bN, wn);
    int ko   = (w >> 2) * 2;

    float acc[4][4][4];
#pragma unroll
    for (int i = 0; i < 4; i++)
#pragma unroll
        for (int j = 0; j < 4; j++)
#pragma unroll
            for (int k = 0; k < 4; k++) acc[i][j][k] = 0.f;

    int ld_row = tid >> 3, ld_c16_8 = (tid & 7) * 8;
    uint32_t so0 = SWZ((uint32_t)(ld_row * 128 + ld_c16_8 * 2));
    const __nv_bfloat16* baA[4];
    const __nv_bfloat16* baB[4];
    uint32_t soi[4];
#pragma unroll
    for (int i = 0; i < 4; i++) {
        int row = ld_row + i * 32;
        baA[i] = g_Abf + (size_t)(bM + row) * KSA1;
        baB[i] = g_Bbf + (size_t)(bN + row) * KB1;
        soi[i] = so0 + (uint32_t)i * 32 * 128;
    }

    auto issue = [&](int c, int b) {
        uint32_t sA = sbase + (uint32_t)b * STG_BYTES;
        int v  = c * 64 + ld_c16_8;
        int sa = (c >= 10) ? v - KSA1 : v;   // uniform third-term wrap
#pragma unroll
        for (int i = 0; i < 4; i++) {
            cpasync16(sA + soi[i],          baA[i] + sa);
            cpasync16(sA + 16384 + soi[i],  baB[i] + v);
        }
        CP_COMMIT();
    };

    issue(0, 0); issue(1, 1);
    for (int c = 0; c < NC1; c++) {
        if (c + 1 < NC1) { CP_WAIT1(); } else { CP_WAIT0(); }
        __syncthreads();
        if (c + 2 < NC1) issue(c + 2, (c + 2) % 3);
        mma_chunk(sbase + (uint32_t)(c % 3) * STG_BYTES, L, acc, nlim, ko);
    }

    int r0 = lane >> 2, cB = (lane & 3) * 2;
#pragma unroll
    for (int mi = 0; mi < 4; mi++) {
        int row = bM + wm + mi * 16 + r0;
#pragma unroll
        for (int nb = 0; nb < 4; nb++) {
            int col = bN + wn + nb * 8 + cB;
            if (row < VOCAB)
                *(float2*)(g_P + (size_t)row * GN + col)
                    = make_float2(acc[mi][nb][0], acc[mi][nb][1]);
            if (row + 8 < VOCAB)
                *(float2*)(g_P + (size_t)(row + 8) * GN + col)
                    = make_float2(acc[mi][nb][2], acc[mi][nb][3]);
        }
    }
}

// ---------------------------------------------------------------------------
// Kernel 2: assemble conv rows -> bf16 split [hi|lo] of g_Cbf. 2 rows/block.
// ---------------------------------------------------------------------------
__global__ __launch_bounds__(256) void assemble_kernel(const int* __restrict__ title,
                                                       const float* __restrict__ conv_b)
{
    int tid  = threadIdx.x;
    int half = tid >> 7;          // 0/1
    int t2   = tid & 127;
    if (t2 >= FILT / 4) return;
    int m   = blockIdx.x * 2 + half;
    int n   = m % SEQ;
    int off = t2 * 4;

    float4 acc = *(const float4*)(conv_b + off);

    int tcur = title[m];
    float4 x = *(const float4*)(g_P + (size_t)tcur * GN + 1 * FILT + off);
    acc.x += x.x; acc.y += x.y; acc.z += x.z; acc.w += x.w;

    if (n > 0) {
        int tp = title[m - 1];
        float4 y = *(const float4*)(g_P + (size_t)tp * GN + 0 * FILT + off);
        acc.x += y.x; acc.y += y.y; acc.z += y.z; acc.w += y.w;
    }
    if (n < SEQ - 1) {
        int tn = title[m + 1];
        float4 z = *(const float4*)(g_P + (size_t)tn * GN + 2 * FILT + off);
        acc.x += z.x; acc.y += z.y; acc.z += z.z; acc.w += z.w;
    }
    acc.x = fmaxf(acc.x, 0.f); acc.y = fmaxf(acc.y, 0.f);
    acc.z = fmaxf(acc.z, 0.f); acc.w = fmaxf(acc.w, 0.f);

    float vv[4] = {acc.x, acc.y, acc.z, acc.w};
    unsigned short hu[4], lu[4];
#pragma unroll
    for (int i = 0; i < 4; i++) {
        __nv_bfloat16 h = __float2bfloat16(vv[i]);
        float lo = vv[i] - __bfloat162float(h);
        hu[i] = __bfloat16_as_ushort(h);
        lu[i] = __bfloat16_as_ushort(__float2bfloat16(lo));
    }
    uint2 hv = make_uint2((uint32_t)hu[0] | ((uint32_t)hu[1] << 16),
                          (uint32_t)hu[2] | ((uint32_t)hu[3] << 16));
    uint2 lv = make_uint2((uint32_t)lu[0] | ((uint32_t)lu[1] << 16),
                          (uint32_t)lu[2] | ((uint32_t)lu[3] << 16));
    __nv_bfloat16* cb = g_Cbf + (size_t)m * KSA2;
    *(uint2*)(cb + off)       = hv;
    *(uint2*)(cb + 400 + off) = lv;
    // cols 800..831 stay zero (zero-init) — virtual-pad source for att GEMM.
}

// ---------------------------------------------------------------------------
// GEMM 3 (HMMA) + fused attention epilogue.
// ---------------------------------------------------------------------------
__global__ __launch_bounds__(256, 2) void gemm_att_mma()
{
    extern __shared__ __align__(128) uint8_t dyn[];
    int tid = threadIdx.x, w = tid >> 5, lane = tid & 31;
    int bM = blockIdx.y * 128, bN = blockIdx.x * 128;
    int wm = (w & 1) * 64, wn = (w >> 1) * 32;
    uint32_t sbase = smem_u32(dyn);
    LdmAddr L = make_ldm(wm, wn, lane);
    int nlim = nlim_of(NREAL2, bN, wn);
    int ko   = (w >> 2) * 2;

    float acc[4][4][4];
#pragma unroll
    for (int i = 0; i < 4; i++)
#pragma unroll
        for (int j = 0; j < 4; j++)
#pragma unroll
            for (int k = 0; k < 4; k++) acc[i][j][k] = 0.f;

    int ld_row = tid >> 3, ld_c16_8 = (tid & 7) * 8;
    uint32_t so0 = SWZ((uint32_t)(ld_row * 128 + ld_c16_8 * 2));
    const __nv_bfloat16* baA[4];
    const __nv_bfloat16* baB[4];
    uint32_t soi[4];
#pragma unroll
    for (int i = 0; i < 4; i++) {
        int row = ld_row + i * 32;
        baA[i] = g_Cbf  + (size_t)(bM + row) * KSA2;
        baB[i] = g_VPbf + (size_t)(bN + row) * KB2;
        soi[i] = so0 + (uint32_t)i * 32 * 128;
    }

    auto issue = [&](int c, int b) {
        uint32_t sA = sbase + (uint32_t)b * STG_BYTES;
        int v  = c * 64 + ld_c16_8;
        // virtual->stored: [0,800)->v, [800,1200)->v-800, [1200,1216)->zeros
        int sa = (v < 800) ? v : ((v < 1200) ? v - 800 : v - 400);
#pragma unroll
        for (int i = 0; i < 4; i++) {
            cpasync16(sA + soi[i],         baA[i] + sa);
            cpasync16(sA + 16384 + soi[i], baB[i] + v);
        }
        CP_COMMIT();
    };

    issue(0, 0); issue(1, 1);
    for (int c = 0; c < NC2; c++) {
        if (c + 1 < NC2) { CP_WAIT1(); } else { CP_WAIT0(); }
        __syncthreads();
        if (c + 2 < NC2) issue(c + 2, (c + 2) % 3);
        mma_chunk(sbase + (uint32_t)(c % 3) * STG_BYTES, L, acc, nlim, ko);
    }

    // Fused epilogue: per-row sum of tanh(S+vb)*q over this block's 128 cols.
    // Zero-padded cols: acc=0, vb=0, q=0 -> contribute exactly 0.
    float rp[4][2];
#pragma unroll
    for (int mi = 0; mi < 4; mi++) { rp[mi][0] = 0.f; rp[mi][1] = 0.f; }
#pragma unroll
    for (int nb = 0; nb < 4; nb++) {
        int gc = bN + wn + nb * 8 + (lane & 3) * 2;
        float vb0 = g_vbp[gc], vb1 = g_vbp[gc + 1];
        float q0  = g_qp[gc],  q1  = g_qp[gc + 1];
#pragma unroll
        for (int mi = 0; mi < 4; mi++) {
            rp[mi][0] += tanhf(acc[mi][nb][0] + vb0) * q0
                       + tanhf(acc[mi][nb][1] + vb1) * q1;
            rp[mi][1] += tanhf(acc[mi][nb][2] + vb0) * q0
                       + tanhf(acc[mi][nb][3] + vb1) * q1;
        }
    }
#pragma unroll
    for (int mi = 0; mi < 4; mi++)
#pragma unroll
        for (int h = 0; h < 2; h++) {
            rp[mi][h] += __shfl_xor_sync(0xffffffffu, rp[mi][h], 1);
            rp[mi][h] += __shfl_xor_sync(0xffffffffu, rp[mi][h], 2);
        }

    __syncthreads();              // tile SMEM reads complete
    float* red = (float*)dyn;     // reuse tile SMEM for the reduction
    if ((lane & 3) == 0) {
#pragma unroll
        for (int mi = 0; mi < 4; mi++)
#pragma unroll
            for (int h = 0; h < 2; h++) {
                int row = wm + mi * 16 + (lane >> 2) + h * 8;
                red[row * 4 + (w >> 1)] = rp[mi][h];
            }
    }
    __syncthreads();
    if (tid < 128) {
        float s = red[tid * 4 + 0] + red[tid * 4 + 1]
                + red[tid * 4 + 2] + red[tid * 4 + 3];
        g_scorep[(size_t)blockIdx.x * M2 + bM + tid] = s;
    }
}

// ---------------------------------------------------------------------------
// Kernel 4: softmax over batch dim (per position n), masked.
// ---------------------------------------------------------------------------
__global__ void softmax_kernel(const int* __restrict__ title)
{
    int n   = blockIdx.x;
    int tid = threadIdx.x;
    __shared__ float red[256];

    float mx = -3.4e38f;
    for (int b = tid; b < BATCH; b += 256) {
        int m = b * SEQ + n;
        float s = g_scorep[m] + g_scorep[M2 + m];
        mx = fmaxf(mx, s);
    }
    red[tid] = mx;
    __syncthreads();
    for (int off = 128; off > 0; off >>= 1) {
        if (tid < off) red[tid] = fmaxf(red[tid], red[tid + off]);
        __syncthreads();
    }
    mx = red[0];
    __syncthreads();

    float sum = 0.f;
    for (int b = tid; b < BATCH; b += 256) {
        int m = b * SEQ + n;
        float s = g_scorep[m] + g_scorep[M2 + m];
        sum += expf(s - mx);
    }
    red[tid] = sum;
    __syncthreads();
    for (int off = 128; off > 0; off >>= 1) {
        if (tid < off) red[tid] += red[tid + off];
        __syncthreads();
    }
    float inv = 1.f / red[0];

    for (int b = tid; b < BATCH; b += 256) {
        int m = b * SEQ + n;
        float s  = g_scorep[m] + g_scorep[M2 + m];
        float al = expf(s - mx) * inv;
        if (title[m] == 0) al = 0.f;
        g_alpha[m] = al;
    }
}

// ---------------------------------------------------------------------------
// Kernel 5: pooling  out[b][f] = sum_n alpha[b,n] * (Cbf_hi + Cbf_lo)[b,n,f]
// ---------------------------------------------------------------------------
__global__ void pool_kernel(float* __restrict__ out)
{
    int b   = blockIdx.x;
    int tid = threadIdx.x;
    __shared__ float al[SEQ];
    if (tid < SEQ) al[tid] = g_alpha[b * SEQ + tid];
    __syncthreads();
    if (tid >= FILT / 4) return;
    int off = tid * 4;
    const __nv_bfloat16* base = g_Cbf + (size_t)b * SEQ * KSA2 + off;
    float4 acc = make_float4(0.f, 0.f, 0.f, 0.f);
#pragma unroll
    for (int n = 0; n < SEQ; n++) {
        float a = al[n];
        const __nv_bfloat16* row = base + (size_t)n * KSA2;
        __nv_bfloat162 h0 = *(const __nv_bfloat162*)(row);
        __nv_bfloat162 h1 = *(const __nv_bfloat162*)(row + 2);
        __nv_bfloat162 l0 = *(const __nv_bfloat162*)(row + 400);
        __nv_bfloat162 l1 = *(const __nv_bfloat162*)(row + 402);
        acc.x = fmaf(a, __bfloat162float(h0.x) + __bfloat162float(l0.x), acc.x);
        acc.y = fmaf(a, __bfloat162float(h0.y) + __bfloat162float(l0.y), acc.y);
        acc.z = fmaf(a, __bfloat162float(h1.x) + __bfloat162float(l1.x), acc.z);
        acc.w = fmaf(a, __bfloat162float(h1.y) + __bfloat162float(l1.y), acc.w);
    }
    *(float4*)(out + (size_t)b * FILT + off) = acc;
}

// ---------------------------------------------------------------------------
// Launch
// ---------------------------------------------------------------------------
extern "C" void kernel_launch(void* const* d_in, const int* in_sizes, int n_in,
                              void* d_out, int out_size)
{
    const int*   title  = (const int*)  d_in[0];
    const float* emb    = (const float*)d_in[1];
    const float* conv_w = (const float*)d_in[2];
    const float* conv_b = (const float*)d_in[3];
    const float* v      = (const float*)d_in[4];
    const float* vb     = (const float*)d_in[5];
    const float* q      = (const float*)d_in[6];
    float*       out    = (float*)d_out;

    cudaFuncSetAttribute(gemm_P_mma,   cudaFuncAttributeMaxDynamicSharedMemorySize, DYN_SMEM);
    cudaFuncSetAttribute(gemm_att_mma, cudaFuncAttributeMaxDynamicSharedMemorySize, DYN_SMEM);

    prep_kernel<<<2048, 256>>>(emb, conv_w, v, vb, q);

    dim3 g1(GN / 128, MPAD / 128);                   // (10, 391)
    gemm_P_mma<<<g1, 256, DYN_SMEM>>>();

    assemble_kernel<<<M2 / 2, 256>>>(title, conv_b);

    dim3 g3(NPAD / 128, M2 / 128);                   // (2, 960)
    gemm_att_mma<<<g3, 256, DYN_SMEM>>>();

    softmax_kernel<<<SEQ, 256>>>(title);

    pool_kernel<<<BATCH, 128>>>(out);
}

// round 15
// speedup vs baseline: 1.0983x; 1.0983x over previous
#include <cuda_runtime.h>
#include <cuda_bf16.h>
#include <cstdint>

// Problem constants
#define VOCAB 50000
#define MPAD  50048              // 391 * 128
#define EMB   300
#define FILT  400
#define ATT   200
#define KW    3
#define BATCH 4096
#define SEQ   30
#define M2    (BATCH * SEQ)      // 122880
#define GN    1280               // 3*400 padded to 1280
#define NPAD  256                // ATT padded 200 -> 256

// GEMM1: virtual K = 960 (3 terms x 320); A stored as [hi|lo] = 640 cols,
//        third (hi) term redirected to cols 0..319 (uniform wrap at c>=10).
#define KV1   960
#define KSA1  640
#define KB1   960
#define NC1   15                 // 960/64
#define NREAL1 1200              // real N columns of gemm_P output
// GEMM2: virtual K = 1216 (hi|lo|hi|pad16); A stored as [hi|lo|zero32] = 832.
#define KV2   1216
#define KSA2  832
#define KB2   1216
#define NC2   19                 // 1216/64
#define NREAL2 200               // real attention columns

// ---------------------------------------------------------------------------
// Scratch (static device globals; zero-initialized at module load)
// ---------------------------------------------------------------------------
__device__ __nv_bfloat16 g_Abf[(size_t)MPAD * KSA1]; // emb split [hi|lo]
__device__ __nv_bfloat16 g_Bbf[(size_t)GN * KB1];    // G split  [hi;hi;lo], [N][K]
__device__ float         g_P[(size_t)VOCAB * GN];    // vocab projection fp32
__device__ __nv_bfloat16 g_Cbf[(size_t)M2 * KSA2];   // relu(conv) split [hi|lo|0]
__device__ __nv_bfloat16 g_VPbf[(size_t)NPAD * KB2]; // v split [hi|hi|lo|0], [N][K]
__device__ float         g_vbp[NPAD];
__device__ float         g_qp[NPAD];
__device__ float         g_scorep[2 * M2];
__device__ float         g_alpha[M2];

// ---------------------------------------------------------------------------
// Kernel 0: build bf16-split operands + padded attention weights (32-bit idx).
// ---------------------------------------------------------------------------
__global__ void prep_kernel(const float* __restrict__ emb,
                            const float* __restrict__ conv_w,
                            const float* __restrict__ v,
                            const float* __restrict__ vb,
                            const float* __restrict__ q)
{
    uint32_t i      = blockIdx.x * blockDim.x + threadIdx.x;
    uint32_t stride = gridDim.x * blockDim.x;

    // A' = emb split: [hi (0..319) | lo (320..639)]; pad k 300..319 zero
    for (uint32_t idx = i; idx < (uint32_t)VOCAB * KSA1; idx += stride) {
        uint32_t m  = idx / KSA1;
        uint32_t kp = idx - m * KSA1;
        uint32_t t  = kp / 320, k = kp - t * 320;
        float out = 0.f;
        if (k < EMB) {
            float x  = emb[m * EMB + k];
            float hi = __bfloat162float(__float2bfloat16(x));
            out = t ? (x - hi) : hi;
        }
        g_Abf[idx] = __float2bfloat16(out);
    }

    // B' = G split, N-major: n = kk*400+f, G[k][n] = conv_w[f][k][kk]; {hi,hi,lo}
    for (uint32_t idx = i; idx < (uint32_t)GN * KB1; idx += stride) {
        uint32_t n  = idx / KB1;
        uint32_t kp = idx - n * KB1;
        uint32_t t  = kp / 320, k = kp - t * 320;
        float out = 0.f;
        if (k < EMB && n < KW * FILT) {
            uint32_t kk = n / FILT, f = n - kk * FILT;
            float x  = conv_w[f * (EMB * KW) + k * KW + kk];
            float hi = __bfloat162float(__float2bfloat16(x));
            out = (t == 2) ? (x - hi) : hi;
        }
        g_Bbf[idx] = __float2bfloat16(out);
    }

    // VP' = v split, N-major: VP'[a][t*400+f] from v[f][a]; {hi,hi,lo}
    for (uint32_t idx = i; idx < (uint32_t)NPAD * KB2; idx += stride) {
        uint32_t a  = idx / KB2;
        uint32_t kp = idx - a * KB2;
        float out = 0.f;
        if (kp < 1200 && a < ATT) {
            uint32_t t = kp / 400, f = kp - t * 400;
            float x  = v[f * ATT + a];
            float hi = __bfloat162float(__float2bfloat16(x));
            out = (t == 2) ? (x - hi) : hi;
        }
        g_VPbf[idx] = __float2bfloat16(out);
    }

    if (i < NPAD) {
        g_vbp[i] = (i < ATT) ? vb[i] : 0.f;
        g_qp[i]  = (i < ATT) ? q[i]  : 0.f;
    }
}

// ---------------------------------------------------------------------------
// HMMA helpers (sm_80-era instructions: compile on family target)
// ---------------------------------------------------------------------------
__device__ __forceinline__ uint32_t smem_u32(const void* p) {
    uint32_t r;
    asm("{ .reg .u64 t; cvta.to.shared.u64 t, %1; cvt.u32.u64 %0, t; }"
        : "=r"(r) : "l"(p));
    return r;
}
#define SWZ(x) ((x) ^ (((x) >> 3) & 0x70))

__device__ __forceinline__ void ldm4(uint32_t* r, uint32_t addr) {
    asm volatile("ldmatrix.sync.aligned.m8n8.x4.shared.b16 {%0,%1,%2,%3}, [%4];"
                 : "=r"(r[0]), "=r"(r[1]), "=r"(r[2]), "=r"(r[3]) : "r"(addr));
}
__device__ __forceinline__ void mma16816(float* c, const uint32_t* a,
                                         uint32_t b0, uint32_t b1) {
    asm volatile(
        "mma.sync.aligned.m16n8k16.row.col.f32.bf16.bf16.f32 "
        "{%0,%1,%2,%3}, {%4,%5,%6,%7}, {%8,%9}, {%0,%1,%2,%3};"
        : "+f"(c[0]), "+f"(c[1]), "+f"(c[2]), "+f"(c[3])
        : "r"(a[0]), "r"(a[1]), "r"(a[2]), "r"(a[3]), "r"(b0), "r"(b1));
}
__device__ __forceinline__ void cpasync16(uint32_t s, const void* g) {
    asm volatile(
        "{ .reg .u64 ga; cvta.to.global.u64 ga, %1; "
        "cp.async.cg.shared.global [%0], [ga], 16; }"
        :: "r"(s), "l"(g) : "memory");
}
#define CP_COMMIT() asm volatile("cp.async.commit_group;" ::: "memory")
#define CP_WAIT1()  asm volatile("cp.async.wait_group 1;" ::: "memory")
#define CP_WAIT0()  asm volatile("cp.async.wait_group 0;" ::: "memory")

#define STG_BYTES 32768          // 16KB A + 16KB B per stage
#define DYN_SMEM  (3 * STG_BYTES)

// Loop-invariant ldmatrix address components; warp layout 2(m) x 4(n).
struct LdmAddr {
    uint32_t aoff[4], axm[4];
    uint32_t boff[2], bxm[2];
    uint32_t colk[4];
};
__device__ __forceinline__ LdmAddr make_ldm(int wm, int wn, int lane) {
    LdmAddr L;
#pragma unroll
    for (int mi = 0; mi < 4; mi++) {
        int r = wm + mi * 16 + (lane & 15);
        L.aoff[mi] = (uint32_t)r * 128;
        L.axm[mi]  = ((uint32_t)r << 4) & 0x70;
    }
#pragma unroll
    for (int bj = 0; bj < 2; bj++) {
        int r = wn + bj * 16 + (lane & 15);
        L.boff[bj] = 16384u + (uint32_t)r * 128;
        L.bxm[bj]  = ((uint32_t)r << 4) & 0x70;
    }
#pragma unroll
    for (int ks = 0; ks < 4; ks++)
        L.colk[ks] = (uint32_t)ks * 32 + ((lane >> 4) << 4);
    return L;
}

// Fully-unrolled chunk specialized on the number of real N tiles (0/1/2/4).
// Static bounds only — no runtime indexing, no predication (R14 lesson).
template <int NLIM>
__device__ __forceinline__ void mma_chunk_t(uint32_t sbuf, const LdmAddr& L,
                                            float acc[4][4][4]) {
    if (NLIM == 0) return;
#pragma unroll
    for (int ks = 0; ks < 4; ks++) {
        uint32_t af[4][4], bf2[2][4];
#pragma unroll
        for (int mi = 0; mi < 4; mi++)
            ldm4(af[mi], sbuf + L.aoff[mi] + (L.colk[ks] ^ L.axm[mi]));
        constexpr int NBJ = (NLIM > 2) ? 2 : 1;
#pragma unroll
        for (int bj = 0; bj < NBJ; bj++)
            ldm4(bf2[bj], sbuf + L.boff[bj] + (L.colk[ks] ^ L.bxm[bj]));
#pragma unroll
        for (int mi = 0; mi < 4; mi++)
#pragma unroll
            for (int nb = 0; nb < NLIM; nb++)
                mma16816(acc[mi][nb], af[mi],
                         bf2[nb >> 1][nb & 1], bf2[nb >> 1][(nb & 1) + 2]);
    }
}

// Warp-uniform dispatch over the (few) NLIM values that occur.
__device__ __forceinline__ void mma_chunk_d(uint32_t sbuf, const LdmAddr& L,
                                            float acc[4][4][4], int nlim) {
    if (nlim == 4)      mma_chunk_t<4>(sbuf, L, acc);
    else if (nlim == 2) mma_chunk_t<2>(sbuf, L, acc);
    else if (nlim == 1) mma_chunk_t<1>(sbuf, L, acc);
    // nlim == 0: nothing
}

__device__ __forceinline__ int nlim_of(int nreal, int bN, int wn) {
    int d = nreal - bN - wn;
    int n = (d + 7) >> 3;
    return (n < 0) ? 0 : ((n > 4) ? 4 : n);
}

// ---------------------------------------------------------------------------
// GEMM 1 (HMMA): g_P[50048 x 1280] = A'[.,960]virt @ B'^T, fp32 accum.
// Block 128x128, BK=64, 3-stage cp.async pipeline, single sync per iter.
// ---------------------------------------------------------------------------
__global__ __launch_bounds__(256, 2) void gemm_P_mma()
{
    extern __shared__ __align__(128) uint8_t dyn[];
    int tid = threadIdx.x, w = tid >> 5, lane = tid & 31;
    int bM = blockIdx.y * 128, bN = blockIdx.x * 128;
    int wm = (w & 1) * 64, wn = (w >> 1) * 32;
    uint32_t sbase = smem_u32(dyn);
    LdmAddr L = make_ldm(wm, wn, lane);
    int nlim = nlim_of(NREAL1, bN, wn);   // {4,4,4,4} except last N block {4,2,0,0}

    float acc[4][4][4];
#pragma unroll
    for (int i = 0; i < 4; i++)
#pragma unroll
        for (int j = 0; j < 4; j++)
#pragma unroll
            for (int k = 0; k < 4; k++) acc[i][j][k] = 0.f;

    // Hoisted per-thread load bases (chunk-invariant).
    int ld_row = tid >> 3, ld_c16_8 = (tid & 7) * 8;
    uint32_t so0 = SWZ((uint32_t)(ld_row * 128 + ld_c16_8 * 2));
    const __nv_bfloat16* baA[4];
    const __nv_bfloat16* baB[4];
    uint32_t soi[4];
#pragma unroll
    for (int i = 0; i < 4; i++) {
        int row = ld_row + i * 32;
        baA[i] = g_Abf + (size_t)(bM + row) * KSA1;
        baB[i] = g_Bbf + (size_t)(bN + row) * KB1;
        soi[i] = so0 + (uint32_t)i * 32 * 128;
    }

    auto issue = [&](int c, int b) {
        uint32_t sA = sbase + (uint32_t)b * STG_BYTES;
        int v  = c * 64 + ld_c16_8;
        int sa = (c >= 10) ? v - KSA1 : v;   // uniform third-term wrap
#pragma unroll
        for (int i = 0; i < 4; i++) {
            cpasync16(sA + soi[i],          baA[i] + sa);
            cpasync16(sA + 16384 + soi[i],  baB[i] + v);
        }
        CP_COMMIT();
    };

    issue(0, 0); issue(1, 1);
    for (int c = 0; c < NC1; c++) {
        if (c + 1 < NC1) { CP_WAIT1(); } else { CP_WAIT0(); }
        __syncthreads();                      // stage c ready AND compute(c-1) done
        if (c + 2 < NC1) issue(c + 2, (c + 2) % 3);
        mma_chunk_d(sbase + (uint32_t)(c % 3) * STG_BYTES, L, acc, nlim);
    }

    int r0 = lane >> 2, cB = (lane & 3) * 2;
#pragma unroll
    for (int mi = 0; mi < 4; mi++) {
        int row = bM + wm + mi * 16 + r0;
#pragma unroll
        for (int nb = 0; nb < 4; nb++) {
            int col = bN + wn + nb * 8 + cB;
            if (row < VOCAB)
                *(float2*)(g_P + (size_t)row * GN + col)
                    = make_float2(acc[mi][nb][0], acc[mi][nb][1]);
            if (row + 8 < VOCAB)
                *(float2*)(g_P + (size_t)(row + 8) * GN + col)
                    = make_float2(acc[mi][nb][2], acc[mi][nb][3]);
        }
    }
}

// ---------------------------------------------------------------------------
// Kernel 2: assemble conv rows -> bf16 split [hi|lo] of g_Cbf. 2 rows/block.
// ---------------------------------------------------------------------------
__global__ __launch_bounds__(256) void assemble_kernel(const int* __restrict__ title,
                                                       const float* __restrict__ conv_b)
{
    int tid  = threadIdx.x;
    int half = tid >> 7;          // 0/1
    int t2   = tid & 127;
    if (t2 >= FILT / 4) return;
    int m   = blockIdx.x * 2 + half;
    int n   = m % SEQ;
    int off = t2 * 4;

    float4 acc = *(const float4*)(conv_b + off);

    int tcur = title[m];
    float4 x = *(const float4*)(g_P + (size_t)tcur * GN + 1 * FILT + off);
    acc.x += x.x; acc.y += x.y; acc.z += x.z; acc.w += x.w;

    if (n > 0) {
        int tp = title[m - 1];
        float4 y = *(const float4*)(g_P + (size_t)tp * GN + 0 * FILT + off);
        acc.x += y.x; acc.y += y.y; acc.z += y.z; acc.w += y.w;
    }
    if (n < SEQ - 1) {
        int tn = title[m + 1];
        float4 z = *(const float4*)(g_P + (size_t)tn * GN + 2 * FILT + off);
        acc.x += z.x; acc.y += z.y; acc.z += z.z; acc.w += z.w;
    }
    acc.x = fmaxf(acc.x, 0.f); acc.y = fmaxf(acc.y, 0.f);
    acc.z = fmaxf(acc.z, 0.f); acc.w = fmaxf(acc.w, 0.f);

    float vv[4] = {acc.x, acc.y, acc.z, acc.w};
    unsigned short hu[4], lu[4];
#pragma unroll
    for (int i = 0; i < 4; i++) {
        __nv_bfloat16 h = __float2bfloat16(vv[i]);
        float lo = vv[i] - __bfloat162float(h);
        hu[i] = __bfloat16_as_ushort(h);
        lu[i] = __bfloat16_as_ushort(__float2bfloat16(lo));
    }
    uint2 hv = make_uint2((uint32_t)hu[0] | ((uint32_t)hu[1] << 16),
                          (uint32_t)hu[2] | ((uint32_t)hu[3] << 16));
    uint2 lv = make_uint2((uint32_t)lu[0] | ((uint32_t)lu[1] << 16),
                          (uint32_t)lu[2] | ((uint32_t)lu[3] << 16));
    __nv_bfloat16* cb = g_Cbf + (size_t)m * KSA2;
    *(uint2*)(cb + off)       = hv;
    *(uint2*)(cb + 400 + off) = lv;
    // cols 800..831 stay zero (zero-init) — virtual-pad source for att GEMM.
}

// ---------------------------------------------------------------------------
// GEMM 3 (HMMA) + fused attention epilogue:
//   S = Cbf[122880 x 1216]virt @ VPbf^T[256 x 1216]
//   scorep[col_block][m] = sum_a tanh(S[m,a]+vb[a]) * q[a]
// ---------------------------------------------------------------------------
__global__ __launch_bounds__(256, 2) void gemm_att_mma()
{
    extern __shared__ __align__(128) uint8_t dyn[];
    int tid = threadIdx.x, w = tid >> 5, lane = tid & 31;
    int bM = blockIdx.y * 128, bN = blockIdx.x * 128;
    int wm = (w & 1) * 64, wn = (w >> 1) * 32;
    uint32_t sbase = smem_u32(dyn);
    LdmAddr L = make_ldm(wm, wn, lane);
    int nlim = nlim_of(NREAL2, bN, wn);   // bN=0: {4,4,4,4}; bN=128: {4,4,1,0}

    float acc[4][4][4];
#pragma unroll
    for (int i = 0; i < 4; i++)
#pragma unroll
        for (int j = 0; j < 4; j++)
#pragma unroll
            for (int k = 0; k < 4; k++) acc[i][j][k] = 0.f;

    int ld_row = tid >> 3, ld_c16_8 = (tid & 7) * 8;
    uint32_t so0 = SWZ((uint32_t)(ld_row * 128 + ld_c16_8 * 2));
    const __nv_bfloat16* baA[4];
    const __nv_bfloat16* baB[4];
    uint32_t soi[4];
#pragma unroll
    for (int i = 0; i < 4; i++) {
        int row = ld_row + i * 32;
        baA[i] = g_Cbf  + (size_t)(bM + row) * KSA2;
        baB[i] = g_VPbf + (size_t)(bN + row) * KB2;
        soi[i] = so0 + (uint32_t)i * 32 * 128;
    }

    auto issue = [&](int c, int b) {
        uint32_t sA = sbase + (uint32_t)b * STG_BYTES;
        int v  = c * 64 + ld_c16_8;
        // virtual->stored: [0,800)->v, [800,1200)->v-800, [1200,1216)->zeros
        int sa = (v < 800) ? v : ((v < 1200) ? v - 800 : v - 400);
#pragma unroll
        for (int i = 0; i < 4; i++) {
            cpasync16(sA + soi[i],         baA[i] + sa);
            cpasync16(sA + 16384 + soi[i], baB[i] + v);
        }
        CP_COMMIT();
    };

    issue(0, 0); issue(1, 1);
    for (int c = 0; c < NC2; c++) {
        if (c + 1 < NC2) { CP_WAIT1(); } else { CP_WAIT0(); }
        __syncthreads();
        if (c + 2 < NC2) issue(c + 2, (c + 2) % 3);
        mma_chunk_d(sbase + (uint32_t)(c % 3) * STG_BYTES, L, acc, nlim);
    }

    // Fused epilogue: per-row sum of tanh(S+vb)*q over this block's 128 cols.
    // Skipped/padded cols: acc=0 and vb=q=0 -> contribute exactly 0.
    float rp[4][2];
#pragma unroll
    for (int mi = 0; mi < 4; mi++) { rp[mi][0] = 0.f; rp[mi][1] = 0.f; }
#pragma unroll
    for (int nb = 0; nb < 4; nb++) {
        int gc = bN + wn + nb * 8 + (lane & 3) * 2;
        float vb0 = g_vbp[gc], vb1 = g_vbp[gc + 1];
        float q0  = g_qp[gc],  q1  = g_qp[gc + 1];
#pragma unroll
        for (int mi = 0; mi < 4; mi++) {
            rp[mi][0] += tanhf(acc[mi][nb][0] + vb0) * q0
                       + tanhf(acc[mi][nb][1] + vb1) * q1;
            rp[mi][1] += tanhf(acc[mi][nb][2] + vb0) * q0
                       + tanhf(acc[mi][nb][3] + vb1) * q1;
        }
    }
#pragma unroll
    for (int mi = 0; mi < 4; mi++)
#pragma unroll
        for (int h = 0; h < 2; h++) {
            rp[mi][h] += __shfl_xor_sync(0xffffffffu, rp[mi][h], 1);
            rp[mi][h] += __shfl_xor_sync(0xffffffffu, rp[mi][h], 2);
        }

    __syncthreads();              // tile SMEM reads complete
    float* red = (float*)dyn;     // reuse tile SMEM for the reduction
    if ((lane & 3) == 0) {
#pragma unroll
        for (int mi = 0; mi < 4; mi++)
#pragma unroll
            for (int h = 0; h < 2; h++) {
                int row = wm + mi * 16 + (lane >> 2) + h * 8;
                red[row * 4 + (w >> 1)] = rp[mi][h];
            }
    }
    __syncthreads();
    if (tid < 128) {
        float s = red[tid * 4 + 0] + red[tid * 4 + 1]
                + red[tid * 4 + 2] + red[tid * 4 + 3];
        g_scorep[(size_t)blockIdx.x * M2 + bM + tid] = s;
    }
}

// ---------------------------------------------------------------------------
// Kernel 4: softmax over batch dim (per position n), masked.
// ---------------------------------------------------------------------------
__global__ void softmax_kernel(const int* __restrict__ title)
{
    int n   = blockIdx.x;
    int tid = threadIdx.x;
    __shared__ float red[256];

    float mx = -3.4e38f;
    for (int b = tid; b < BATCH; b += 256) {
        int m = b * SEQ + n;
        float s = g_scorep[m] + g_scorep[M2 + m];
        mx = fmaxf(mx, s);
    }
    red[tid] = mx;
    __syncthreads();
    for (int off = 128; off > 0; off >>= 1) {
        if (tid < off) red[tid] = fmaxf(red[tid], red[tid + off]);
        __syncthreads();
    }
    mx = red[0];
    __syncthreads();

    float sum = 0.f;
    for (int b = tid; b < BATCH; b += 256) {
        int m = b * SEQ + n;
        float s = g_scorep[m] + g_scorep[M2 + m];
        sum += expf(s - mx);
    }
    red[tid] = sum;
    __syncthreads();
    for (int off = 128; off > 0; off >>= 1) {
        if (tid < off) red[tid] += red[tid + off];
        __syncthreads();
    }
    float inv = 1.f / red[0];

    for (int b = tid; b < BATCH; b += 256) {
        int m = b * SEQ + n;
        float s  = g_scorep[m] + g_scorep[M2 + m];
        float al = expf(s - mx) * inv;
        if (title[m] == 0) al = 0.f;
        g_alpha[m] = al;
    }
}

// ---------------------------------------------------------------------------
// Kernel 5: pooling  out[b][f] = sum_n alpha[b,n] * (Cbf_hi + Cbf_lo)[b,n,f]
// ---------------------------------------------------------------------------
__global__ void pool_kernel(float* __restrict__ out)
{
    int b   = blockIdx.x;
    int tid = threadIdx.x;
    __shared__ float al[SEQ];
    if (tid < SEQ) al[tid] = g_alpha[b * SEQ + tid];
    __syncthreads();
    if (tid >= FILT / 4) return;
    int off = tid * 4;
    const __nv_bfloat16* base = g_Cbf + (size_t)b * SEQ * KSA2 + off;
    float4 acc = make_float4(0.f, 0.f, 0.f, 0.f);
#pragma unroll
    for (int n = 0; n < SEQ; n++) {
        float a = al[n];
        const __nv_bfloat16* row = base + (size_t)n * KSA2;
        __nv_bfloat162 h0 = *(const __nv_bfloat162*)(row);
        __nv_bfloat162 h1 = *(const __nv_bfloat162*)(row + 2);
        __nv_bfloat162 l0 = *(const __nv_bfloat162*)(row + 400);
        __nv_bfloat162 l1 = *(const __nv_bfloat162*)(row + 402);
        acc.x = fmaf(a, __bfloat162float(h0.x) + __bfloat162float(l0.x), acc.x);
        acc.y = fmaf(a, __bfloat162float(h0.y) + __bfloat162float(l0.y), acc.y);
        acc.z = fmaf(a, __bfloat162float(h1.x) + __bfloat162float(l1.x), acc.z);
        acc.w = fmaf(a, __bfloat162float(h1.y) + __bfloat162float(l1.y), acc.w);
    }
    *(float4*)(out + (size_t)b * FILT + off) = acc;
}

// ---------------------------------------------------------------------------
// Launch
// ---------------------------------------------------------------------------
extern "C" void kernel_launch(void* const* d_in, const int* in_sizes, int n_in,
                              void* d_out, int out_size)
{
    const int*   title  = (const int*)  d_in[0];
    const float* emb    = (const float*)d_in[1];
    const float* conv_w = (const float*)d_in[2];
    const float* conv_b = (const float*)d_in[3];
    const float* v      = (const float*)d_in[4];
    const float* vb     = (const float*)d_in[5];
    const float* q      = (const float*)d_in[6];
    float*       out    = (float*)d_out;

    cudaFuncSetAttribute(gemm_P_mma,   cudaFuncAttributeMaxDynamicSharedMemorySize, DYN_SMEM);
    cudaFuncSetAttribute(gemm_att_mma, cudaFuncAttributeMaxDynamicSharedMemorySize, DYN_SMEM);

    prep_kernel<<<2048, 256>>>(emb, conv_w, v, vb, q);

    dim3 g1(GN / 128, MPAD / 128);                   // (10, 391)
    gemm_P_mma<<<g1, 256, DYN_SMEM>>>();

    assemble_kernel<<<M2 / 2, 256>>>(title, conv_b);

    dim3 g3(NPAD / 128, M2 / 128);                   // (2, 960)
    gemm_att_mma<<<g3, 256, DYN_SMEM>>>();

    softmax_kernel<<<SEQ, 256>>>(title);

    pool_kernel<<<BATCH, 128>>>(out);
}